// round 10
// baseline (speedup 1.0000x reference)
#include <cuda_runtime.h>

#define W_IMG 3840
#define H_IMG 2160
#define TILE_W 30            // output columns per warp (lanes 1..30)
#define NW_X 128             // 3840 / 30
#define NW_Y 46              // vertical strips (47 or 46 rows)
#define WPB 8
#define NTHREADS 256
#define NBLOCKS ((NW_X * NW_Y) / WPB)   // 736 blocks -> one wave at 5/SM

__device__ double g_num;
__device__ unsigned int g_cnt;
__device__ unsigned int g_ticket;

__constant__ float c_l[27];
__constant__ float c_Kc[9];

__launch_bounds__(NTHREADS, 5)
__global__ void shading_loss_kernel(const float* __restrict__ depth,
                                    const float* __restrict__ rgb,
                                    const int*   __restrict__ mask,
                                    float* __restrict__ out)
{
    const int tid  = threadIdx.x;
    const int lane = tid & 31;
    const int w    = tid >> 5;
    const int wid  = blockIdx.x * WPB + w;
    const int tx   = wid % NW_X;
    const int ty   = wid / NW_X;
    // 2160 = 44*47 + 2*46 : first 44 strips are 47 rows tall
    const int r0   = ty * 46 + min(ty, 44);
    const int hgt  = 46 + (ty < 44 ? 1 : 0);
    const int c0   = tx * TILE_W;
    const int col  = c0 - 1 + lane;
    const bool colin  = (col >= 0) && (col < W_IMG);
    const bool colrin = (col + 1 < W_IMG);
    const bool safe   = (tx >= 1) && (tx <= NW_X - 2) && (ty >= 1) && (ty <= NW_Y - 2);

    // camera inverse (adjugate) from constant bank — uniform arithmetic
    float a = c_Kc[0], b = c_Kc[1], cc = c_Kc[2];
    float d = c_Kc[3], e = c_Kc[4], f  = c_Kc[5];
    float g = c_Kc[6], h = c_Kc[7], i  = c_Kc[8];
    float A =  (e*i - f*h), B = -(d*i - f*g), C =  (d*h - e*g);
    float inv = 1.0f / (a*A + b*B + cc*C);
    const float K0 = A*inv,  K1 = -(b*i - cc*h)*inv,  K2 =  (b*f - cc*e)*inv;
    const float K3 = B*inv,  K4 =  (a*i - cc*g)*inv,  K5 = -(a*f - cc*d)*inv;
    const float K6 = C*inv,  K7 = -(a*h - b*g)*inv,   K8 =  (a*e - b*d)*inv;

    const float x = (float)col;
    float rx = K0 * x + K1 * (float)(r0 - 1) + K2;
    float ry = K3 * x + K4 * (float)(r0 - 1) + K5;
    float rz = K6 * x + K7 * (float)(r0 - 1) + K8;

    float acc = 0.0f;
    unsigned int cnt = 0;
    const bool emitlane = (lane >= 1) && (lane <= 30);
    const float inv9 = 1.0f / 9.0f;
    const int rend = r0 + hgt;

    float hsA0,hsA1,hsA2, hsB0,hsB1,hsB2;
    float qC0,qC1,qC2;
    int   mC;

// shade current row from (dA, dB, dR, m, rg*) -> q*, hs*, advance ray; dA<-dB
#define SHADE_CORE                                                            \
    float b0 = 0.0f, b1 = 0.0f, b2 = 0.0f;                                   \
    if (m) {                                                                 \
        float px = rx * dA, py = ry * dA, pz = rz * dA;                      \
        float axv = (rx + K0) * dR - px, ayv = (ry + K3) * dR - py, azv = (rz + K6) * dR - pz; \
        float bxv = (rx + K1) * dB - px, byv = (ry + K4) * dB - py, bzv = (rz + K7) * dB - pz; \
        float nx = ayv * bzv - azv * byv;                                    \
        float ny = azv * bxv - axv * bzv;                                    \
        float nz = axv * byv - ayv * bxv;                                    \
        float nn = nx*nx + ny*ny + nz*nz;                                    \
        float invn = rsqrtf(fmaxf(nn, 1e-24f));                              \
        nx *= invn; ny *= invn; nz *= invn;                                  \
        float nx2 = nx*nx, ny2 = ny*ny, nz2 = nz*nz;                         \
        float H1 = ny, H2 = nz, H3 = nx;                                     \
        float H4 = nx*ny, H5 = ny*nz;                                        \
        float H6 = 2.0f*nz2 - nx2 - ny2;                                     \
        float H7 = nz*nx, H8 = nx2 - ny2;                                    \
        b0 = c_l[0] + H1*c_l[3]  + H2*c_l[6]  + H3*c_l[9]  + H4*c_l[12] + H5*c_l[15] + H6*c_l[18] + H7*c_l[21] + H8*c_l[24]; \
        b1 = c_l[1] + H1*c_l[4]  + H2*c_l[7]  + H3*c_l[10] + H4*c_l[13] + H5*c_l[16] + H6*c_l[19] + H7*c_l[22] + H8*c_l[25]; \
        b2 = c_l[2] + H1*c_l[5]  + H2*c_l[8]  + H3*c_l[11] + H4*c_l[14] + H5*c_l[17] + H6*c_l[20] + H7*c_l[23] + H8*c_l[26]; \
    }                                                                        \
    float q0 = b0 - rg0, q1 = b1 - rg1, q2 = b2 - rg2;                       \
    float hs0, hs1, hs2;                                                     \
    {                                                                        \
        float ql0 = __shfl_up_sync(0xffffffffu, q0, 1), qr0 = __shfl_down_sync(0xffffffffu, q0, 1); \
        float ql1 = __shfl_up_sync(0xffffffffu, q1, 1), qr1 = __shfl_down_sync(0xffffffffu, q1, 1); \
        float ql2 = __shfl_up_sync(0xffffffffu, q2, 1), qr2 = __shfl_down_sync(0xffffffffu, q2, 1); \
        hs0 = ql0 + q0 + qr0;                                                \
        hs1 = ql1 + q1 + qr1;                                                \
        hs2 = ql2 + q2 + qr2;                                                \
    }                                                                        \
    dA = dB;                                                                 \
    rx += K1; ry += K4; rz += K7;

#define EMIT                                                                  \
    if (emitlane && mC) {                                                    \
        float d0 = qC0 - (hsA0 + hsB0 + hs0) * inv9;                         \
        float d1 = qC1 - (hsA1 + hsB1 + hs1) * inv9;                         \
        float d2 = qC2 - (hsA2 + hsB2 + hs2) * inv9;                         \
        acc += d0*d0 + d1*d1 + d2*d2;                                        \
        cnt += 1u;                                                           \
    }

#define ROTATE                                                                \
    hsA0 = hsB0; hsA1 = hsB1; hsA2 = hsB2;                                   \
    hsB0 = hs0;  hsB1 = hs1;  hsB2 = hs2;                                    \
    qC0 = q0; qC1 = q1; qC2 = q2; mC = m;

// prefetch one row's operands into *_n registers, then advance off
#define PREFETCH_SAFE                                                         \
    dB_n = depth[off + W_IMG];                                               \
    dR_n = depth[off + 1];                                                   \
    m_n  = mask[off] > 0;                                                    \
    { int ro3 = off * 3;                                                     \
      rg0_n = rgb[ro3]; rg1_n = rgb[ro3 + 1]; rg2_n = rgb[ro3 + 2]; }        \
    off += W_IMG;

// consume prefetched operands into current-row locals
#define CONSUME                                                               \
    float dB = dB_n, dR = dR_n;                                              \
    int   m  = m_n;                                                          \
    float rg0 = rg0_n, rg1 = rg1_n, rg2 = rg2_n;

    if (safe) {
        int off = (r0 - 1) * W_IMG + col;
        float dA = depth[off];
        float dB_n, dR_n, rg0_n, rg1_n, rg2_n;
        int m_n;
        PREFETCH_SAFE;                               // loads for row r0-1

        // warm-up row r0-1
        { CONSUME; PREFETCH_SAFE; SHADE_CORE;
          hsA0 = hs0; hsA1 = hs1; hsA2 = hs2; (void)q0; (void)m; }
        // warm-up row r0
        { CONSUME; PREFETCH_SAFE; SHADE_CORE;
          hsB0 = hs0; hsB1 = hs1; hsB2 = hs2;
          qC0 = q0; qC1 = q1; qC2 = q2; mC = m; }
        // steady rows r0+1 .. rend-1 : consume, prefetch next, shade, emit
        #pragma unroll 2
        for (int r = r0 + 1; r < rend; ++r) {
            CONSUME;
            PREFETCH_SAFE;                           // row r+1 (<= rend, in-image)
            SHADE_CORE;
            EMIT;
            ROTATE;
        }
        // final row rend: consume only (no prefetch past the strip)
        { CONSUME; SHADE_CORE; EMIT; ROTATE; (void)m; }
    } else {
        int off = (r0 - 1) * W_IMG + col;
        float dA = 0.0f;
        if (colin && r0 >= 1) dA = depth[off];

#define ROW_GEN                                                               \
    const bool rin  = ((unsigned)r < (unsigned)H_IMG);                       \
    const bool rnin = ((unsigned)(r + 1) < (unsigned)H_IMG);                 \
    float dB = (rnin && colin)  ? depth[off + W_IMG] : 0.0f;                 \
    float dR = (rin  && colrin) ? depth[off + 1]     : 0.0f;                 \
    int   m  = 0;                                                            \
    float rg0 = 0.0f, rg1 = 0.0f, rg2 = 0.0f;                                \
    if (rin && colin) {                                                      \
        m = mask[off] > 0;                                                   \
        int ro3 = off * 3;                                                   \
        rg0 = rgb[ro3]; rg1 = rgb[ro3 + 1]; rg2 = rgb[ro3 + 2];              \
    }                                                                        \
    off += W_IMG;                                                            \
    SHADE_CORE

        { int r = r0 - 1; ROW_GEN; hsA0 = hs0; hsA1 = hs1; hsA2 = hs2; (void)m; }
        { int r = r0;     ROW_GEN; hsB0 = hs0; hsB1 = hs1; hsB2 = hs2;
          qC0 = q0; qC1 = q1; qC2 = q2; mC = m; }
        #pragma unroll 1
        for (int r = r0 + 1; r <= rend; ++r) {
            ROW_GEN;
            EMIT;
            ROTATE;
        }
    }

    // ---- reduction: warp -> block -> global ----
    #pragma unroll
    for (int o = 16; o > 0; o >>= 1) {
        acc += __shfl_down_sync(0xffffffffu, acc, o);
        cnt += __shfl_down_sync(0xffffffffu, cnt, o);
    }
    __shared__ float s_red[WPB];
    __shared__ unsigned int s_redc[WPB];
    if (lane == 0) { s_red[w] = acc; s_redc[w] = cnt; }
    __syncthreads();
    if (tid == 0) {
        float aa = 0.0f; unsigned int cn = 0;
        #pragma unroll
        for (int k = 0; k < WPB; k++) { aa += s_red[k]; cn += s_redc[k]; }
        atomicAdd(&g_num, (double)aa);
        atomicAdd(&g_cnt, cn);
        __threadfence();
        unsigned int t = atomicAdd(&g_ticket, 1u);
        if (t == NBLOCKS - 1) {
            __threadfence();
            double num = g_num;
            unsigned int c2 = g_cnt;
            out[0] = (float)(num / ((double)c2 * 3.0));
            g_num = 0.0;
            g_cnt = 0u;
            g_ticket = 0u;
        }
    }
}

extern "C" void kernel_launch(void* const* d_in, const int* in_sizes, int n_in,
                              void* d_out, int out_size) {
    const float* depth = (const float*)d_in[0];
    const float* rgb   = (const float*)d_in[1];
    const int*   mask  = (const int*)d_in[2];
    const float* l     = (const float*)d_in[3];
    const float* Kc    = (const float*)d_in[4];

    cudaMemcpyToSymbolAsync(c_l,  l,  27 * sizeof(float), 0, cudaMemcpyDeviceToDevice);
    cudaMemcpyToSymbolAsync(c_Kc, Kc,  9 * sizeof(float), 0, cudaMemcpyDeviceToDevice);

    shading_loss_kernel<<<NBLOCKS, NTHREADS>>>(depth, rgb, mask, (float*)d_out);
}

// round 11
// speedup vs baseline: 1.0664x; 1.0664x over previous
#include <cuda_runtime.h>

#define W_IMG 3840
#define H_IMG 2160
#define TILE_W 30            // output columns per warp (lanes 1..30)
#define NW_X 128             // 3840 / 30
#define NW_Y 46              // vertical strips (47 or 46 rows)
#define WPB 8
#define NTHREADS 256
#define NBLOCKS ((NW_X * NW_Y) / WPB)   // 736 blocks -> one wave at 5/SM

__device__ double g_num;
__device__ unsigned int g_cnt;
__device__ unsigned int g_ticket;

__constant__ float c_l[27];
__constant__ float c_Kc[9];

__launch_bounds__(NTHREADS, 5)
__global__ void shading_loss_kernel(const float* __restrict__ depth,
                                    const float* __restrict__ rgb,
                                    const int*   __restrict__ mask,
                                    float* __restrict__ out)
{
    const int tid  = threadIdx.x;
    const int lane = tid & 31;
    const int w    = tid >> 5;
    const int wid  = blockIdx.x * WPB + w;
    const int tx   = wid % NW_X;
    const int ty   = wid / NW_X;
    // 2160 = 44*47 + 2*46 : first 44 strips are 47 rows tall
    const int r0   = ty * 46 + min(ty, 44);
    const int hgt  = 46 + (ty < 44 ? 1 : 0);
    const int c0   = tx * TILE_W;
    const int col  = c0 - 1 + lane;
    const bool colin  = (col >= 0) && (col < W_IMG);
    const bool colrin = (col + 1 < W_IMG);
    const bool safe   = (tx >= 1) && (tx <= NW_X - 2) && (ty >= 1) && (ty <= NW_Y - 2);

    // camera inverse (adjugate) from constant bank — uniform arithmetic
    float a = c_Kc[0], b = c_Kc[1], cc = c_Kc[2];
    float d = c_Kc[3], e = c_Kc[4], f  = c_Kc[5];
    float g = c_Kc[6], h = c_Kc[7], i  = c_Kc[8];
    float A =  (e*i - f*h), B = -(d*i - f*g), C =  (d*h - e*g);
    float inv = 1.0f / (a*A + b*B + cc*C);
    const float K0 = A*inv,  K1 = -(b*i - cc*h)*inv,  K2 =  (b*f - cc*e)*inv;
    const float K3 = B*inv,  K4 =  (a*i - cc*g)*inv,  K5 = -(a*f - cc*d)*inv;
    const float K6 = C*inv,  K7 = -(a*h - b*g)*inv,   K8 =  (a*e - b*d)*inv;

    // ray at (col, r0-1): R = Kinv (x, y, 1)
    const float x = (float)col;
    const float y0 = (float)(r0 - 1);
    const float Rx = K0 * x + K1 * y0 + K2;
    const float Ry = K3 * x + K4 * y0 + K5;
    const float Rz = K6 * x + K7 * y0 + K8;

    // n = u*[dl(d0-du)] + v*[du(dl-d0)] + w*[dl*du]
    // u = R x e0 (updates u -= w per row), v = R x e1 (const), w = e0 x e1 (const)
    float ux = Ry * K6 - Rz * K3;
    float uy = Rz * K0 - Rx * K6;
    float uz = Rx * K3 - Ry * K0;
    const float vx = Ry * K7 - Rz * K4;
    const float vy = Rz * K1 - Rx * K7;
    const float vz = Rx * K4 - Ry * K1;
    const float wx = K3 * K7 - K6 * K4;
    const float wy = K6 * K1 - K0 * K7;
    const float wz = K0 * K4 - K3 * K1;

    float acc = 0.0f;
    unsigned int cnt = 0;
    const bool emitlane = (lane >= 1) && (lane <= 30);
    const float inv9 = 1.0f / 9.0f;
    const int rend = r0 + hgt;

    float hsA0,hsA1,hsA2, hsB0,hsB1,hsB2;
    float qC0,qC1,qC2;
    int   mC;

#define ROW_SAFE                                                              \
    float dB = depth[off + W_IMG];                                           \
    float dR = depth[off + 1];                                               \
    int   m  = mask[off] > 0;                                                \
    int ro3 = off * 3;                                                       \
    float rg0 = rgb[ro3], rg1 = rgb[ro3 + 1], rg2 = rgb[ro3 + 2];            \
    SHADE_BODY

#define ROW_GEN                                                               \
    const bool rin  = ((unsigned)r < (unsigned)H_IMG);                       \
    const bool rnin = ((unsigned)(r + 1) < (unsigned)H_IMG);                 \
    float dB = (rnin && colin)  ? depth[off + W_IMG] : 0.0f;                 \
    float dR = (rin  && colrin) ? depth[off + 1]     : 0.0f;                 \
    int   m  = 0;                                                            \
    float rg0 = 0.0f, rg1 = 0.0f, rg2 = 0.0f;                                \
    if (rin && colin) {                                                      \
        m = mask[off] > 0;                                                   \
        int ro3 = off * 3;                                                   \
        rg0 = rgb[ro3]; rg1 = rgb[ro3 + 1]; rg2 = rgb[ro3 + 2];              \
    }                                                                        \
    SHADE_BODY

#define SHADE_BODY                                                            \
    float b0 = 0.0f, b1 = 0.0f, b2 = 0.0f;                                   \
    if (m) {                                                                 \
        float s1 = dR * (dA - dB);                                           \
        float s2 = dB * (dR - dA);                                           \
        float s3 = dR * dB;                                                  \
        float nx = ux * s1 + vx * s2 + wx * s3;                              \
        float ny = uy * s1 + vy * s2 + wy * s3;                              \
        float nz = uz * s1 + vz * s2 + wz * s3;                              \
        float nn = nx*nx + ny*ny + nz*nz;                                    \
        float invn = rsqrtf(fmaxf(nn, 1e-24f));                              \
        nx *= invn; ny *= invn; nz *= invn;                                  \
        float nx2 = nx*nx, ny2 = ny*ny, nz2 = nz*nz;                         \
        float H1 = ny, H2 = nz, H3 = nx;                                     \
        float H4 = nx*ny, H5 = ny*nz;                                        \
        float H6 = 2.0f*nz2 - nx2 - ny2;                                     \
        float H7 = nz*nx, H8 = nx2 - ny2;                                    \
        b0 = c_l[0] + H1*c_l[3]  + H2*c_l[6]  + H3*c_l[9]  + H4*c_l[12] + H5*c_l[15] + H6*c_l[18] + H7*c_l[21] + H8*c_l[24]; \
        b1 = c_l[1] + H1*c_l[4]  + H2*c_l[7]  + H3*c_l[10] + H4*c_l[13] + H5*c_l[16] + H6*c_l[19] + H7*c_l[22] + H8*c_l[25]; \
        b2 = c_l[2] + H1*c_l[5]  + H2*c_l[8]  + H3*c_l[11] + H4*c_l[14] + H5*c_l[17] + H6*c_l[20] + H7*c_l[23] + H8*c_l[26]; \
    }                                                                        \
    float q0 = b0 - rg0, q1 = b1 - rg1, q2 = b2 - rg2;                       \
    float hs0, hs1, hs2;                                                     \
    {                                                                        \
        float ql0 = __shfl_up_sync(0xffffffffu, q0, 1), qr0 = __shfl_down_sync(0xffffffffu, q0, 1); \
        float ql1 = __shfl_up_sync(0xffffffffu, q1, 1), qr1 = __shfl_down_sync(0xffffffffu, q1, 1); \
        float ql2 = __shfl_up_sync(0xffffffffu, q2, 1), qr2 = __shfl_down_sync(0xffffffffu, q2, 1); \
        hs0 = ql0 + q0 + qr0;                                                \
        hs1 = ql1 + q1 + qr1;                                                \
        hs2 = ql2 + q2 + qr2;                                                \
    }                                                                        \
    dA = dB;                                                                 \
    off += W_IMG;                                                            \
    ux -= wx; uy -= wy; uz -= wz;

#define EMIT                                                                  \
    if (emitlane && mC) {                                                    \
        float d0 = qC0 - (hsA0 + hsB0 + hs0) * inv9;                         \
        float d1 = qC1 - (hsA1 + hsB1 + hs1) * inv9;                         \
        float d2 = qC2 - (hsA2 + hsB2 + hs2) * inv9;                         \
        acc += d0*d0 + d1*d1 + d2*d2;                                        \
        cnt += 1u;                                                           \
    }

#define ROTATE                                                                \
    hsA0 = hsB0; hsA1 = hsB1; hsA2 = hsB2;                                   \
    hsB0 = hs0;  hsB1 = hs1;  hsB2 = hs2;                                    \
    qC0 = q0; qC1 = q1; qC2 = q2; mC = m;

    if (safe) {
        int off = (r0 - 1) * W_IMG + col;
        float dA = depth[off];
        { ROW_SAFE; hsA0 = hs0; hsA1 = hs1; hsA2 = hs2; (void)m; }
        { ROW_SAFE; hsB0 = hs0; hsB1 = hs1; hsB2 = hs2;
          qC0 = q0; qC1 = q1; qC2 = q2; mC = m; }
        #pragma unroll 2
        for (int r = r0 + 1; r <= rend; ++r) {
            ROW_SAFE;
            EMIT;
            ROTATE;
        }
    } else {
        int off = (r0 - 1) * W_IMG + col;
        float dA = 0.0f;
        if (colin && r0 >= 1) dA = depth[off];
        { int r = r0 - 1; ROW_GEN; hsA0 = hs0; hsA1 = hs1; hsA2 = hs2; (void)m; }
        { int r = r0;     ROW_GEN; hsB0 = hs0; hsB1 = hs1; hsB2 = hs2;
          qC0 = q0; qC1 = q1; qC2 = q2; mC = m; }
        #pragma unroll 1
        for (int r = r0 + 1; r <= rend; ++r) {
            ROW_GEN;
            EMIT;
            ROTATE;
        }
    }

    // ---- reduction: warp -> block -> global ----
    #pragma unroll
    for (int o = 16; o > 0; o >>= 1) {
        acc += __shfl_down_sync(0xffffffffu, acc, o);
        cnt += __shfl_down_sync(0xffffffffu, cnt, o);
    }
    __shared__ float s_red[WPB];
    __shared__ unsigned int s_redc[WPB];
    if (lane == 0) { s_red[w] = acc; s_redc[w] = cnt; }
    __syncthreads();
    if (tid == 0) {
        float aa = 0.0f; unsigned int cn = 0;
        #pragma unroll
        for (int k = 0; k < WPB; k++) { aa += s_red[k]; cn += s_redc[k]; }
        atomicAdd(&g_num, (double)aa);
        atomicAdd(&g_cnt, cn);
        __threadfence();
        unsigned int t = atomicAdd(&g_ticket, 1u);
        if (t == NBLOCKS - 1) {
            __threadfence();
            double num = g_num;
            unsigned int c2 = g_cnt;
            out[0] = (float)(num / ((double)c2 * 3.0));
            g_num = 0.0;
            g_cnt = 0u;
            g_ticket = 0u;
        }
    }
}

extern "C" void kernel_launch(void* const* d_in, const int* in_sizes, int n_in,
                              void* d_out, int out_size) {
    const float* depth = (const float*)d_in[0];
    const float* rgb   = (const float*)d_in[1];
    const int*   mask  = (const int*)d_in[2];
    const float* l     = (const float*)d_in[3];
    const float* Kc    = (const float*)d_in[4];

    cudaMemcpyToSymbolAsync(c_l,  l,  27 * sizeof(float), 0, cudaMemcpyDeviceToDevice);
    cudaMemcpyToSymbolAsync(c_Kc, Kc,  9 * sizeof(float), 0, cudaMemcpyDeviceToDevice);

    shading_loss_kernel<<<NBLOCKS, NTHREADS>>>(depth, rgb, mask, (float*)d_out);
}

// round 12
// speedup vs baseline: 1.0956x; 1.0274x over previous
#include <cuda_runtime.h>

#define W_IMG 3840
#define H_IMG 2160
#define OUT_W 60             // output columns per warp (lane pairs 1..30)
#define NW_X 64              // 3840 / 60
#define NW_Y 74              // vertical strips (30 or 29 rows)
#define WPB 8
#define NTHREADS 256
#define NBLOCKS ((NW_X * NW_Y) / WPB)   // 592 = 148 SMs x 4 blocks, one wave

__device__ double g_num;
__device__ unsigned int g_cnt;
__device__ unsigned int g_ticket;

__constant__ float c_l[27];
__constant__ float c_Kc[9];

__launch_bounds__(NTHREADS, 4)
__global__ void shading_loss_kernel(const float* __restrict__ depth,
                                    const float* __restrict__ rgb,
                                    const int*   __restrict__ mask,
                                    float* __restrict__ out)
{
    const int tid  = threadIdx.x;
    const int lane = tid & 31;
    const int w    = tid >> 5;
    const int wid  = blockIdx.x * WPB + w;
    const int tx   = wid % NW_X;
    const int ty   = wid / NW_X;
    // 2160 = 14*30 + 60*29 : first 14 strips are 30 rows tall
    const int r0   = ty * 29 + min(ty, 14);
    const int hgt  = 29 + (ty < 14 ? 1 : 0);
    const int c0   = tx * OUT_W;
    const int colA = c0 - 2 + 2 * lane;    // even
    const int colB = colA + 1;
    const bool colinA = (colA >= 0) && (colA < W_IMG);
    const bool colinB = (colB >= 0) && (colB < W_IMG);
    const bool safe   = (tx >= 1) && (tx <= NW_X - 2) && (ty >= 1) && (ty <= NW_Y - 2);

    // camera inverse (adjugate) from constant bank — uniform arithmetic
    float a = c_Kc[0], b = c_Kc[1], cc = c_Kc[2];
    float d = c_Kc[3], e = c_Kc[4], f  = c_Kc[5];
    float g = c_Kc[6], h = c_Kc[7], i  = c_Kc[8];
    float A =  (e*i - f*h), B = -(d*i - f*g), C =  (d*h - e*g);
    float inv = 1.0f / (a*A + b*B + cc*C);
    const float K0 = A*inv,  K1 = -(b*i - cc*h)*inv,  K2 =  (b*f - cc*e)*inv;
    const float K3 = B*inv,  K4 =  (a*i - cc*g)*inv,  K5 = -(a*f - cc*d)*inv;
    const float K6 = C*inv,  K7 = -(a*h - b*g)*inv,   K8 =  (a*e - b*d)*inv;

    // ray for column A at row r0-1 (column B ray = ray + (K0,K3,K6))
    const float xA = (float)colA;
    const float y0 = (float)(r0 - 1);
    float rx = K0 * xA + K1 * y0 + K2;
    float ry = K3 * xA + K4 * y0 + K5;
    float rz = K6 * xA + K7 * y0 + K8;

    float acc = 0.0f;
    unsigned int cnt = 0;
    const bool emitlane = (lane >= 1) && (lane <= 30);
    const float inv9 = 1.0f / 9.0f;
    const int rend = r0 + hgt;

    // vertical pipeline state (per column, per channel)
    float h2a0,h2a1,h2a2, h2b0,h2b1,h2b2;   // hsum(row r-2)
    float h1a0,h1a1,h1a2, h1b0,h1b1,h1b2;   // hsum(row r-1)
    float qCa0,qCa1,qCa2, qCb0,qCb1,qCb2;   // q(row r-1)
    int   mCa, mCb;
    float dA_a, dA_b;                        // depth(row r)

// shade one column: inputs (ray, d0, right-depth, down-depth, mask, rgb) -> q
#define SHADE1(qq0,qq1,qq2, rxv,ryv,rzv, d0,dl,du, mm_, rr0,rr1,rr2)          \
  {                                                                           \
    float b0=0.f,b1=0.f,b2=0.f;                                               \
    if (mm_) {                                                                \
      float px=(rxv)*(d0), py=(ryv)*(d0), pz=(rzv)*(d0);                      \
      float axv=((rxv)+K0)*(dl)-px, ayv=((ryv)+K3)*(dl)-py, azv=((rzv)+K6)*(dl)-pz; \
      float bxv=((rxv)+K1)*(du)-px, byv=((ryv)+K4)*(du)-py, bzv=((rzv)+K7)*(du)-pz; \
      float nx=ayv*bzv-azv*byv, ny=azv*bxv-axv*bzv, nz=axv*byv-ayv*bxv;       \
      float nn=nx*nx+ny*ny+nz*nz;                                             \
      float invn=rsqrtf(fmaxf(nn,1e-24f));                                    \
      nx*=invn; ny*=invn; nz*=invn;                                           \
      float nx2=nx*nx, ny2=ny*ny, nz2=nz*nz;                                  \
      float H1=ny,H2=nz,H3=nx,H4=nx*ny,H5=ny*nz;                              \
      float H6=2.f*nz2-nx2-ny2, H7=nz*nx, H8=nx2-ny2;                         \
      b0=c_l[0]+H1*c_l[3]+H2*c_l[6]+H3*c_l[9]+H4*c_l[12]+H5*c_l[15]+H6*c_l[18]+H7*c_l[21]+H8*c_l[24]; \
      b1=c_l[1]+H1*c_l[4]+H2*c_l[7]+H3*c_l[10]+H4*c_l[13]+H5*c_l[16]+H6*c_l[19]+H7*c_l[22]+H8*c_l[25]; \
      b2=c_l[2]+H1*c_l[5]+H2*c_l[8]+H3*c_l[11]+H4*c_l[14]+H5*c_l[17]+H6*c_l[20]+H7*c_l[23]+H8*c_l[26]; \
    }                                                                         \
    qq0=b0-(rr0); qq1=b1-(rr1); qq2=b2-(rr2);                                 \
  }

// horizontal sums from (qa, qb): hsa center=colA, hsb center=colB
#define HSUMS                                                                 \
    float pb0 = __shfl_up_sync(0xffffffffu, qb0, 1);                          \
    float pb1 = __shfl_up_sync(0xffffffffu, qb1, 1);                          \
    float pb2 = __shfl_up_sync(0xffffffffu, qb2, 1);                          \
    float na0 = __shfl_down_sync(0xffffffffu, qa0, 1);                        \
    float na1 = __shfl_down_sync(0xffffffffu, qa1, 1);                        \
    float na2 = __shfl_down_sync(0xffffffffu, qa2, 1);                        \
    float hsa0 = pb0+qa0+qb0, hsa1 = pb1+qa1+qb1, hsa2 = pb2+qa2+qb2;         \
    float hsb0 = qa0+qb0+na0, hsb1 = qa1+qb1+na1, hsb2 = qa2+qb2+na2;

#define ROW_SAFE                                                              \
    float2 dBv = *reinterpret_cast<const float2*>(depth + off + W_IMG);       \
    int2   mmv = *reinterpret_cast<const int2*>(mask + off);                  \
    const float* rp = rgb + off * 3;                                          \
    float2 f0 = *reinterpret_cast<const float2*>(rp);                         \
    float2 f1 = *reinterpret_cast<const float2*>(rp + 2);                     \
    float2 f2 = *reinterpret_cast<const float2*>(rp + 4);                     \
    float dRa = dA_b;                                                         \
    float dRb = __shfl_down_sync(0xffffffffu, dA_a, 1);                       \
    int ma = mmv.x > 0, mb = mmv.y > 0;                                       \
    float qa0,qa1,qa2, qb0,qb1,qb2;                                           \
    SHADE1(qa0,qa1,qa2, rx,ry,rz,          dA_a,dRa,dBv.x, ma, f0.x,f0.y,f1.x); \
    SHADE1(qb0,qb1,qb2, rx+K0,ry+K3,rz+K6, dA_b,dRb,dBv.y, mb, f1.y,f2.x,f2.y); \
    HSUMS;                                                                    \
    dA_a = dBv.x; dA_b = dBv.y;                                               \
    off += W_IMG;                                                             \
    rx += K1; ry += K4; rz += K7;

#define ROW_GEN                                                               \
    const bool rin  = ((unsigned)r < (unsigned)H_IMG);                        \
    const bool rnin = ((unsigned)(r + 1) < (unsigned)H_IMG);                  \
    float dBa = (rnin && colinA) ? depth[off + W_IMG]     : 0.0f;             \
    float dBb = (rnin && colinB) ? depth[off + W_IMG + 1] : 0.0f;             \
    int ma = 0, mb = 0;                                                       \
    float ra0=0.f,ra1=0.f,ra2=0.f, rb0=0.f,rb1=0.f,rb2=0.f;                   \
    if (rin && colinA) { ma = mask[off] > 0; int o3 = off * 3;                \
        ra0 = rgb[o3]; ra1 = rgb[o3+1]; ra2 = rgb[o3+2]; }                    \
    if (rin && colinB) { mb = mask[off+1] > 0; int o3 = (off+1) * 3;          \
        rb0 = rgb[o3]; rb1 = rgb[o3+1]; rb2 = rgb[o3+2]; }                    \
    float dRa = dA_b;                                                         \
    float dRb = __shfl_down_sync(0xffffffffu, dA_a, 1);                       \
    float qa0,qa1,qa2, qb0,qb1,qb2;                                           \
    SHADE1(qa0,qa1,qa2, rx,ry,rz,          dA_a,dRa,dBa, ma, ra0,ra1,ra2);    \
    SHADE1(qb0,qb1,qb2, rx+K0,ry+K3,rz+K6, dA_b,dRb,dBb, mb, rb0,rb1,rb2);    \
    HSUMS;                                                                    \
    dA_a = dBa; dA_b = dBb;                                                   \
    off += W_IMG;                                                             \
    rx += K1; ry += K4; rz += K7;

#define EMIT                                                                  \
    if (emitlane) {                                                           \
        if (mCa) {                                                            \
            float d0 = qCa0 - (h2a0 + h1a0 + hsa0) * inv9;                    \
            float d1 = qCa1 - (h2a1 + h1a1 + hsa1) * inv9;                    \
            float d2 = qCa2 - (h2a2 + h1a2 + hsa2) * inv9;                    \
            acc += d0*d0 + d1*d1 + d2*d2;                                     \
            cnt += 1u;                                                        \
        }                                                                     \
        if (mCb) {                                                            \
            float d0 = qCb0 - (h2b0 + h1b0 + hsb0) * inv9;                    \
            float d1 = qCb1 - (h2b1 + h1b1 + hsb1) * inv9;                    \
            float d2 = qCb2 - (h2b2 + h1b2 + hsb2) * inv9;                    \
            acc += d0*d0 + d1*d1 + d2*d2;                                     \
            cnt += 1u;                                                        \
        }                                                                     \
    }

#define ROTATE                                                                \
    h2a0=h1a0; h2a1=h1a1; h2a2=h1a2; h2b0=h1b0; h2b1=h1b1; h2b2=h1b2;         \
    h1a0=hsa0; h1a1=hsa1; h1a2=hsa2; h1b0=hsb0; h1b1=hsb1; h1b2=hsb2;         \
    qCa0=qa0; qCa1=qa1; qCa2=qa2; qCb0=qb0; qCb1=qb1; qCb2=qb2;               \
    mCa=ma; mCb=mb;

    if (safe) {
        int off = (r0 - 1) * W_IMG + colA;
        float2 dv = *reinterpret_cast<const float2*>(depth + off);
        dA_a = dv.x; dA_b = dv.y;
        // warm-up row r0-1 -> h2
        { ROW_SAFE;
          h2a0=hsa0; h2a1=hsa1; h2a2=hsa2; h2b0=hsb0; h2b1=hsb1; h2b2=hsb2;
          (void)ma; (void)mb; }
        // warm-up row r0 -> h1, qC, mC
        { ROW_SAFE;
          h1a0=hsa0; h1a1=hsa1; h1a2=hsa2; h1b0=hsb0; h1b1=hsb1; h1b2=hsb2;
          qCa0=qa0; qCa1=qa1; qCa2=qa2; qCb0=qb0; qCb1=qb1; qCb2=qb2;
          mCa=ma; mCb=mb; }
        #pragma unroll 2
        for (int r = r0 + 1; r <= rend; ++r) {
            ROW_SAFE;
            EMIT;
            ROTATE;
        }
    } else {
        int off = (r0 - 1) * W_IMG + colA;
        dA_a = 0.0f; dA_b = 0.0f;
        if (r0 >= 1) {
            if (colinA) dA_a = depth[off];
            if (colinB) dA_b = depth[off + 1];
        }
        { int r = r0 - 1; ROW_GEN;
          h2a0=hsa0; h2a1=hsa1; h2a2=hsa2; h2b0=hsb0; h2b1=hsb1; h2b2=hsb2;
          (void)ma; (void)mb; }
        { int r = r0; ROW_GEN;
          h1a0=hsa0; h1a1=hsa1; h1a2=hsa2; h1b0=hsb0; h1b1=hsb1; h1b2=hsb2;
          qCa0=qa0; qCa1=qa1; qCa2=qa2; qCb0=qb0; qCb1=qb1; qCb2=qb2;
          mCa=ma; mCb=mb; }
        #pragma unroll 1
        for (int r = r0 + 1; r <= rend; ++r) {
            ROW_GEN;
            EMIT;
            ROTATE;
        }
    }

    // ---- reduction: warp -> block -> global ----
    #pragma unroll
    for (int o = 16; o > 0; o >>= 1) {
        acc += __shfl_down_sync(0xffffffffu, acc, o);
        cnt += __shfl_down_sync(0xffffffffu, cnt, o);
    }
    __shared__ float s_red[WPB];
    __shared__ unsigned int s_redc[WPB];
    if (lane == 0) { s_red[w] = acc; s_redc[w] = cnt; }
    __syncthreads();
    if (tid == 0) {
        float aa = 0.0f; unsigned int cn = 0;
        #pragma unroll
        for (int k = 0; k < WPB; k++) { aa += s_red[k]; cn += s_redc[k]; }
        atomicAdd(&g_num, (double)aa);
        atomicAdd(&g_cnt, cn);
        __threadfence();
        unsigned int t = atomicAdd(&g_ticket, 1u);
        if (t == NBLOCKS - 1) {
            __threadfence();
            double num = g_num;
            unsigned int c2 = g_cnt;
            out[0] = (float)(num / ((double)c2 * 3.0));
            g_num = 0.0;
            g_cnt = 0u;
            g_ticket = 0u;
        }
    }
}

extern "C" void kernel_launch(void* const* d_in, const int* in_sizes, int n_in,
                              void* d_out, int out_size) {
    const float* depth = (const float*)d_in[0];
    const float* rgb   = (const float*)d_in[1];
    const int*   mask  = (const int*)d_in[2];
    const float* l     = (const float*)d_in[3];
    const float* Kc    = (const float*)d_in[4];

    cudaMemcpyToSymbolAsync(c_l,  l,  27 * sizeof(float), 0, cudaMemcpyDeviceToDevice);
    cudaMemcpyToSymbolAsync(c_Kc, Kc,  9 * sizeof(float), 0, cudaMemcpyDeviceToDevice);

    shading_loss_kernel<<<NBLOCKS, NTHREADS>>>(depth, rgb, mask, (float*)d_out);
}